// round 10
// baseline (speedup 1.0000x reference)
#include <cuda_runtime.h>

#define B_WIN 2048
#define NTOK  98
#define NHEAD 4
#define HD    32
#define C3    384
#define DIMM  128
#define NWIN  64
#define NN    (NTOK * NTOK)   // 9604
#define RPB_ROWS 507

typedef unsigned int uint;

// ---------------- bf16 helpers ----------------
__device__ __forceinline__ uint pkbf(float lo, float hi) {
    uint r; asm("cvt.rn.bf16x2.f32 %0, %1, %2;" : "=r"(r) : "f"(hi), "f"(lo)); return r;
}
__device__ __forceinline__ float blo(uint p) { return __uint_as_float(p << 16); }
__device__ __forceinline__ float bhi(uint p) { return __uint_as_float(p & 0xffff0000u); }

// D += A * B  (m16n8k16, bf16 in, f32 accum)
__device__ __forceinline__ void mma16816(float* d, const uint* a, uint b0, uint b1) {
    asm("mma.sync.aligned.m16n8k16.row.col.f32.bf16.bf16.f32 "
        "{%0,%1,%2,%3}, {%4,%5,%6,%7}, {%8,%9}, {%0,%1,%2,%3};"
        : "+f"(d[0]), "+f"(d[1]), "+f"(d[2]), "+f"(d[3])
        : "r"(a[0]), "r"(a[1]), "r"(a[2]), "r"(a[3]), "r"(b0), "r"(b1));
}

// ldmatrix x4: lanes 0-7 address matrix0 rows, 8-15 m1, 16-23 m2, 24-31 m3
__device__ __forceinline__ void ldm4(uint* d, uint addr) {
    asm volatile("ldmatrix.sync.aligned.m8n8.x4.shared.b16 {%0,%1,%2,%3}, [%4];"
        : "=r"(d[0]), "=r"(d[1]), "=r"(d[2]), "=r"(d[3]) : "r"(addr));
}

// ---------------- scratch ----------------
__device__ float g_bm[(size_t)NWIN * NHEAD * NN];   // bias + mask (fp32), 9.8 MB

// smem word offsets (attention phase)
#define QH  0
#define QL  2240
#define KH  4480
#define KL  6720
#define VTH 8960
#define VTL 10880
#define QKVW 12800
// smem word offsets (projection phase, overlays QKV)
#define WH  0
#define WL  8704
#define SMW_TOT 17408   // 69632 B

// ---------------------------------------------------------------------------
// Kernel A: g_bm[w][h][q*98+k] = rpb_table[rpi[q,k]][h] + mask[w][q][k]
// ---------------------------------------------------------------------------
__global__ void bm_kernel(const int* __restrict__ rpi,
                          const float* __restrict__ table,
                          const float* __restrict__ mask) {
    int i = blockIdx.x * blockDim.x + threadIdx.x;
    if (i >= NWIN * NN) return;
    int w = i / NN;
    int e = i - w * NN;
    int r = rpi[e];
    r = (r < 0) ? 0 : (r >= RPB_ROWS ? RPB_ROWS - 1 : r);
    float mk = mask[(size_t)w * NN + e];
#pragma unroll
    for (int hh = 0; hh < NHEAD; hh++) {
        g_bm[((size_t)w * NHEAD + hh) * NN + e] = table[r * NHEAD + hh] + mk;
    }
}

// ---------------------------------------------------------------------------
// Fused kernel: streaming softmax-deferred attention + register projection.
// LDSM operands, chain-parallel compensated MMAs.
// 256 threads, 8 warps (warps 0-6 compute m16 row-blocks; warp 7 load-only).
// ---------------------------------------------------------------------------
__global__ __launch_bounds__(256, 2) void fused_kernel(const float* __restrict__ x,
                                                       const float* __restrict__ pw,
                                                       const float* __restrict__ pb,
                                                       float* __restrict__ out) {
    extern __shared__ uint smw[];

    const int b   = blockIdx.x;
    const int tid = threadIdx.x;
    const int lane = tid & 31;
    const int wid  = tid >> 5;
    const int g = lane >> 2;     // row-in-tile group
    const int t = lane & 3;      // thread in group
    const int l7 = lane & 7;

    const float scale = 0.17677669529663687f;  // 1/sqrt(32)
    const float* xb = x + (size_t)b * NTOK * C3;
    const int r0 = wid * 16 + g;
    const int q1 = r0 + 8;
    const bool rok0 = (r0 < NTOK), rok1 = (q1 < NTOK);

    // ---- per-lane ldmatrix base addresses (shared space, bytes) ----
    // A (Q): m0 rows 0-7 k0-7 | m1 rows 8-15 k0-7 | m2 rows 0-7 k8-15 | m3 rows 8-15 k8-15
    const uint qbase = (uint)__cvta_generic_to_shared(
        smw + QH + (wid * 16 + ((lane >> 3) & 1) * 8 + l7) * 20) + (lane >> 4) * 16;
    // B (K): m0 KH w+0 | m1 KH w+16B | m2 KL w+0 | m3 KL w+16B ; rows l7
    const uint kbase = (uint)__cvta_generic_to_shared(
        smw + ((lane < 16) ? KH : KL) + l7 * 20) + ((lane >> 3) & 1) * 16;
    const uint vbase = (uint)__cvta_generic_to_shared(
        smw + ((lane < 16) ? VTH : VTL) + l7 * 60) + ((lane >> 3) & 1) * 16;
    const uint wbase = (uint)__cvta_generic_to_shared(
        smw + ((lane < 16) ? WH : WL) + l7 * 68) + ((lane >> 3) & 1) * 16;

    // ---- zero QKV region once (covers all row/col pads) ----
    for (int i = tid; i < QKVW; i += 256) smw[i] = 0u;

    // ---- O accumulators: full 128-d for rows r0, q1 ----
    float O[16][4];
#pragma unroll
    for (int nt = 0; nt < 16; nt++)
#pragma unroll
        for (int j = 0; j < 4; j++) O[nt][j] = 0.0f;

#pragma unroll
    for (int h = 0; h < NHEAD; h++) {
        __syncthreads();   // previous head's consumers done (and zero visible)

        // ---- load + split Q(scaled), K, V(transposed) to bf16 hi/lo ----
        for (int i = tid; i < NTOK * 16; i += 256) {
            int q = i >> 4, dp = i & 15;
            const float* base = xb + q * C3 + h * HD + 2 * dp;
            float2 qv = *(const float2*)base;
            qv.x *= scale; qv.y *= scale;
            uint hq = pkbf(qv.x, qv.y);
            smw[QH + q * 20 + dp] = hq;
            smw[QL + q * 20 + dp] = pkbf(qv.x - blo(hq), qv.y - bhi(hq));
            float2 kv = *(const float2*)(base + DIMM);
            uint hk = pkbf(kv.x, kv.y);
            smw[KH + q * 20 + dp] = hk;
            smw[KL + q * 20 + dp] = pkbf(kv.x - blo(hk), kv.y - bhi(hk));
            float2 vv = *(const float2*)(base + 2 * DIMM);
            uint hv = pkbf(vv.x, vv.y);
            uint lv = pkbf(vv.x - blo(hv), vv.y - bhi(hv));
            unsigned short* vth = (unsigned short*)(smw + VTH);
            unsigned short* vtl = (unsigned short*)(smw + VTL);
            int d0 = 2 * dp;
            vth[d0 * 120 + q]       = (unsigned short)(hv & 0xffffu);
            vth[(d0 + 1) * 120 + q] = (unsigned short)(hv >> 16);
            vtl[d0 * 120 + q]       = (unsigned short)(lv & 0xffffu);
            vtl[(d0 + 1) * 120 + q] = (unsigned short)(lv >> 16);
        }
        __syncthreads();

        if (wid < 7) {
            const float* bmp = g_bm + ((size_t)(b & (NWIN - 1)) * NHEAD + h) * NN;
            float s0 = 0.0f, s1 = 0.0f;
            float* Oh = &O[4 * h][0];

            // ---- stream over k16 chunks: S pair -> exp -> pack -> PV ----
#pragma unroll
            for (int c = 0; c < 7; c++) {
                float Sp[2][4];
#pragma unroll
                for (int u = 0; u < 2; u++)
#pragma unroll
                    for (int j = 0; j < 4; j++) Sp[u][j] = 0.0f;

                // K fragments: kf[u] = {bh0,bh1,bl0,bl1} per s
#pragma unroll
                for (int s = 0; s < 2; s++) {
                    uint kf0[4], kf1[4], qh_[4], ql_[4];
                    ldm4(kf0, kbase + (2 * c) * 640 + s * 32);
                    ldm4(kf1, kbase + (2 * c + 1) * 640 + s * 32);
                    ldm4(qh_, qbase + s * 32);
                    ldm4(ql_, qbase + 8960 + s * 32);   // QL region (+2240 words)
                    // variant-major, alternating independent accumulators
                    mma16816(Sp[0], qh_, kf0[0], kf0[1]);
                    mma16816(Sp[1], qh_, kf1[0], kf1[1]);
                    mma16816(Sp[0], qh_, kf0[2], kf0[3]);
                    mma16816(Sp[1], qh_, kf1[2], kf1[3]);
                    mma16816(Sp[0], ql_, kf0[0], kf0[1]);
                    mma16816(Sp[1], ql_, kf1[0], kf1[1]);
                }

                // ---- bias + mask + padding, then exp (no max subtract) ----
#pragma unroll
                for (int u = 0; u < 2; u++) {
                    int nt = 2 * c + u;
                    int c0 = nt * 8 + 2 * t;
                    bool cok = (c0 < NTOK);
                    if (rok0 && cok) {
                        float2 bb = __ldg((const float2*)(bmp + r0 * NTOK + c0));
                        Sp[u][0] += bb.x; Sp[u][1] += bb.y;
                    } else { Sp[u][0] = -1e30f; Sp[u][1] = -1e30f; }
                    if (rok1 && cok) {
                        float2 bb = __ldg((const float2*)(bmp + q1 * NTOK + c0));
                        Sp[u][2] += bb.x; Sp[u][3] += bb.y;
                    } else { Sp[u][2] = -1e30f; Sp[u][3] = -1e30f; }
                    Sp[u][0] = __expf(Sp[u][0]); s0 += Sp[u][0];
                    Sp[u][1] = __expf(Sp[u][1]); s0 += Sp[u][1];
                    Sp[u][2] = __expf(Sp[u][2]); s1 += Sp[u][2];
                    Sp[u][3] = __expf(Sp[u][3]); s1 += Sp[u][3];
                }

                // ---- pack unnormalized P to bf16 hi/lo A-fragment ----
                uint pah[4], pal[4];
                pah[0] = pkbf(Sp[0][0], Sp[0][1]);
                pal[0] = pkbf(Sp[0][0] - blo(pah[0]), Sp[0][1] - bhi(pah[0]));
                pah[1] = pkbf(Sp[0][2], Sp[0][3]);
                pal[1] = pkbf(Sp[0][2] - blo(pah[1]), Sp[0][3] - bhi(pah[1]));
                pah[2] = pkbf(Sp[1][0], Sp[1][1]);
                pal[2] = pkbf(Sp[1][0] - blo(pah[2]), Sp[1][1] - bhi(pah[2]));
                pah[3] = pkbf(Sp[1][2], Sp[1][3]);
                pal[3] = pkbf(Sp[1][2] - blo(pah[3]), Sp[1][3] - bhi(pah[3]));

                // ---- PV accumulate: 4 d-tiles, variant-major (4 chains) ----
                uint vf[4][4];
#pragma unroll
                for (int nt = 0; nt < 4; nt++)
                    ldm4(vf[nt], vbase + nt * 1920 + c * 32);
#pragma unroll
                for (int nt = 0; nt < 4; nt++)
                    mma16816(&Oh[4 * nt], pah, vf[nt][0], vf[nt][1]);
#pragma unroll
                for (int nt = 0; nt < 4; nt++)
                    mma16816(&Oh[4 * nt], pah, vf[nt][2], vf[nt][3]);
#pragma unroll
                for (int nt = 0; nt < 4; nt++)
                    mma16816(&Oh[4 * nt], pal, vf[nt][0], vf[nt][1]);
            }

            // ---- deferred normalization: O *= 1/rowsum ----
            s0 += __shfl_xor_sync(0xffffffffu, s0, 1);
            s0 += __shfl_xor_sync(0xffffffffu, s0, 2);
            s1 += __shfl_xor_sync(0xffffffffu, s1, 1);
            s1 += __shfl_xor_sync(0xffffffffu, s1, 2);
            float inv0 = __frcp_rn(s0), inv1 = __frcp_rn(s1);
#pragma unroll
            for (int nt = 0; nt < 4; nt++) {
                Oh[4 * nt + 0] *= inv0;
                Oh[4 * nt + 1] *= inv0;
                Oh[4 * nt + 2] *= inv1;
                Oh[4 * nt + 3] *= inv1;
            }
        }
    }

    // ================= projection phase =================
    __syncthreads();   // all PV reads of V done before W overwrites smem

    // load + split W: Wh/Wl [128 cols x 68w stride]
    for (int i = tid; i < 8192; i += 256) {
        int c = i >> 6, dp = i & 63;
        float2 w = *(const float2*)(pw + c * DIMM + 2 * dp);
        uint hw_ = pkbf(w.x, w.y);
        smw[WH + c * 68 + dp] = hw_;
        smw[WL + c * 68 + dp] = pkbf(w.x - blo(hw_), w.y - bhi(hw_));
    }
    __syncthreads();

    if (wid >= 7) return;

    // ---- pack O once to bf16 hi/lo A-fragments (replaces O's registers) ----
    uint pA[8][4], pAl[8][4];
#pragma unroll
    for (int s = 0; s < 8; s++) {
        int k0 = 2 * s, k1 = 2 * s + 1;
        pA[s][0]  = pkbf(O[k0][0], O[k0][1]);
        pAl[s][0] = pkbf(O[k0][0] - blo(pA[s][0]), O[k0][1] - bhi(pA[s][0]));
        pA[s][1]  = pkbf(O[k0][2], O[k0][3]);
        pAl[s][1] = pkbf(O[k0][2] - blo(pA[s][1]), O[k0][3] - bhi(pA[s][1]));
        pA[s][2]  = pkbf(O[k1][0], O[k1][1]);
        pAl[s][2] = pkbf(O[k1][0] - blo(pA[s][2]), O[k1][1] - bhi(pA[s][2]));
        pA[s][3]  = pkbf(O[k1][2], O[k1][3]);
        pAl[s][3] = pkbf(O[k1][2] - blo(pA[s][3]), O[k1][3] - bhi(pA[s][3]));
    }

    float* orow0 = out + ((size_t)b * NTOK + r0) * DIMM;
    float* orow1 = out + ((size_t)b * NTOK + q1) * DIMM;

#pragma unroll
    for (int half = 0; half < 2; half++) {
        float R[8][4];
#pragma unroll
        for (int nt = 0; nt < 8; nt++)
#pragma unroll
            for (int j = 0; j < 4; j++) R[nt][j] = 0.0f;

#pragma unroll
        for (int s = 0; s < 8; s++) {
#pragma unroll
            for (int grp = 0; grp < 2; grp++) {
                uint wf[4][4];
#pragma unroll
                for (int i = 0; i < 4; i++)
                    ldm4(wf[i], wbase + (half * 8 + grp * 4 + i) * 2176 + s * 32);
#pragma unroll
                for (int i = 0; i < 4; i++)
                    mma16816(R[grp * 4 + i], pA[s], wf[i][0], wf[i][1]);
#pragma unroll
                for (int i = 0; i < 4; i++)
                    mma16816(R[grp * 4 + i], pA[s], wf[i][2], wf[i][3]);
#pragma unroll
                for (int i = 0; i < 4; i++)
                    mma16816(R[grp * 4 + i], pAl[s], wf[i][0], wf[i][1]);
            }
        }

#pragma unroll
        for (int nt = 0; nt < 8; nt++) {
            int c0 = (half * 8 + nt) * 8 + 2 * t;
            float2 bb = __ldg((const float2*)(pb + c0));
            if (rok0) {
                float2 o0 = { R[nt][0] + bb.x, R[nt][1] + bb.y };
                *(float2*)(orow0 + c0) = o0;
            }
            if (rok1) {
                float2 o1 = { R[nt][2] + bb.x, R[nt][3] + bb.y };
                *(float2*)(orow1 + c0) = o1;
            }
        }
    }
}

// ---------------------------------------------------------------------------
extern "C" void kernel_launch(void* const* d_in, const int* in_sizes, int n_in,
                              void* d_out, int out_size) {
    const float* x     = (const float*)d_in[0];
    const int*   rpi   = (const int*)d_in[1];      // int32 on the wire
    const float* mask  = (const float*)d_in[2];
    const float* table = (const float*)d_in[3];
    const float* pw    = (const float*)d_in[4];
    const float* pb    = (const float*)d_in[5];
    float*       out   = (float*)d_out;

    const int smem_fused = SMW_TOT * 4;   // 69632 B
    cudaFuncSetAttribute(fused_kernel, cudaFuncAttributeMaxDynamicSharedMemorySize, smem_fused);

    bm_kernel<<<(NWIN * NN + 255) / 256, 256>>>(rpi, table, mask);
    fused_kernel<<<B_WIN, 256, smem_fused>>>(x, pw, pb, out);
}